// round 7
// baseline (speedup 1.0000x reference)
#include <cuda_runtime.h>
#include <cuda_bf16.h>
#include <math.h>

#define B_  16
#define C_  256
#define H_  128
#define W_  128
#define K_  12
#define HW_ (H_ * W_)

#define SBAND 4                   // stats: rows per band
#define SBPX  (SBAND * W_)        // 512
#define SWARP 8                   // warps per stats block
#define SCH   16                  // channels per stats warp

#define ABAND 8                   // apply: rows per band
#define ABPX  (ABAND * W_)        // 1024
#define ACH   8                   // channels per apply block (1 per warp)

// ---------------- device scratch ----------------------------------------------
__device__ float g_y[B_ * C_];
__device__ float g_gate[B_ * C_];
__device__ float g_aggw[B_ * C_ * 9];
__device__ float g_ps[2][B_ * HW_];   // partial sum   (per channel-half)
__device__ float g_pq[2][B_ * HW_];   // partial sumsq

__device__ __forceinline__ float sigmoidf_(float v) {
    return 1.0f / (1.0f + __expf(-v));
}

// Juffa-style erff: max ~3 ulp; FMA fast path, __expf tail.
__device__ __forceinline__ float fast_erff(float a) {
    float t = fabsf(a);
    float s = a * a;
    float r;
    if (t > 0.921875f) {
        r = fmaf(-1.72853470e-5f, t, 3.83197126e-4f);
        float u = fmaf(-3.88396438e-3f, t, 2.42546219e-2f);
        r = fmaf(r, s, u);
        r = fmaf(r, t, -1.06952421e-1f);
        r = fmaf(r, t, -6.34846687e-1f);
        r = fmaf(r, t, -1.28717512e-1f);
        r = fmaf(r, t, -t);
        r = 1.0f - __expf(r);
        r = copysignf(r, a);
    } else {
        r = -5.96761703e-4f;
        r = fmaf(r, s,  4.99119423e-3f);
        r = fmaf(r, s, -2.67681349e-2f);
        r = fmaf(r, s,  1.12819925e-1f);
        r = fmaf(r, s, -3.76125336e-1f);
        r = fmaf(r, s,  1.28379166e-1f);
        r = fmaf(r, a, a);
    }
    return r;
}
__device__ __forceinline__ float gelu_f(float v) {
    return 0.5f * v * (1.0f + fast_erff(v * 0.70710678118654752f));
}

// ---------------- K1: global average pool per (b,c) ---------------------------
__global__ void gap_kernel(const float* __restrict__ x) {
    __shared__ float red[8];
    const int bc = blockIdx.x;
    const float4* xp = reinterpret_cast<const float4*>(x + (size_t)bc * HW_);
    float s = 0.f;
#pragma unroll
    for (int i = 0; i < 16; i++) {
        float4 v = xp[threadIdx.x + 256 * i];
        s += (v.x + v.y) + (v.z + v.w);
    }
#pragma unroll
    for (int o = 16; o; o >>= 1) s += __shfl_xor_sync(0xffffffffu, s, o);
    if ((threadIdx.x & 31) == 0) red[threadIdx.x >> 5] = s;
    __syncthreads();
    if (threadIdx.x < 8) {
        s = red[threadIdx.x];
#pragma unroll
        for (int o = 4; o; o >>= 1) s += __shfl_xor_sync(0x000000ffu, s, o);
        if (threadIdx.x == 0) g_y[bc] = s * (1.0f / (float)HW_);
    }
}

// ---------------- K2: ECA gate + MLP + softmax + kernel aggregation -----------
__global__ void attn_kernel(const float* __restrict__ w1, const float* __restrict__ b1,
                            const float* __restrict__ w2, const float* __restrict__ b2,
                            const float* __restrict__ kw, const float* __restrict__ eca) {
    const int b = blockIdx.x;
    const int t = threadIdx.x;
    __shared__ float ysm[C_ + 2];
    __shared__ float psm[C_];
    __shared__ float hsm[C_];
    __shared__ float lsm[K_];
    __shared__ float alph[K_];

    ysm[t + 1] = g_y[b * C_ + t];
    if (t == 0) { ysm[0] = 0.f; ysm[C_ + 1] = 0.f; }
    __syncthreads();

    const float e0 = eca[0], e1 = eca[1], e2 = eca[2];
    float gate = sigmoidf_(e0 * ysm[t] + e1 * ysm[t + 1] + e2 * ysm[t + 2]);
    g_gate[b * C_ + t] = gate;
    psm[t] = gate * ysm[t + 1];
    __syncthreads();

    float acc = b1[t];
    for (int c = 0; c < C_; c++) acc += psm[c] * w1[c * C_ + t];
    hsm[t] = 0.5f * acc * (1.0f + erff(acc * 0.70710678118654752f));
    __syncthreads();

    if (t < K_) {
        float l = b2[t];
        for (int c = 0; c < C_; c++) l += hsm[c] * w2[c * K_ + t];
        lsm[t] = l;
    }
    __syncthreads();

    if (t == 0) {
        float m = lsm[0];
#pragma unroll
        for (int k = 1; k < K_; k++) m = fmaxf(m, lsm[k]);
        float s = 0.f;
#pragma unroll
        for (int k = 0; k < K_; k++) { float e = __expf(lsm[k] - m); alph[k] = e; s += e; }
        float inv = 1.0f / s;
#pragma unroll
        for (int k = 0; k < K_; k++) alph[k] *= inv;
    }
    __syncthreads();

    for (int idx = t; idx < C_ * 9; idx += 256) {
        float v = 0.f;
#pragma unroll
        for (int k = 0; k < K_; k++) v += alph[k] * kw[k * (C_ * 9) + idx];
        g_aggw[b * (C_ * 9) + idx] = v;
    }
}

// ---------------- register sliding-window conv helpers -------------------------
template <int NR> struct WinT { float4 r[NR]; };

template <int NR>
__device__ __forceinline__ void load_winN(const float4* __restrict__ xc4,
                                          int h0, int lane, WinT<NR>& w) {
#pragma unroll
    for (int r = 0; r < NR; r++) {
        const int gh = h0 - 1 + r;
        if (gh >= 0 && gh < H_) w.r[r] = xc4[gh * (W_ / 4) + lane];
        else                    w.r[r] = make_float4(0.f, 0.f, 0.f, 0.f);
    }
}

template <int NR>
__device__ __forceinline__ void shiftsN(const WinT<NR>& win, float* L, float* Rv, int lane) {
#pragma unroll
    for (int r = 0; r < NR; r++) {
        float l  = __shfl_up_sync(0xffffffffu, win.r[r].w, 1);
        float rr = __shfl_down_sync(0xffffffffu, win.r[r].x, 1);
        L[r]  = (lane == 0)  ? 0.f : l;
        Rv[r] = (lane == 31) ? 0.f : rr;
    }
}

template <int NR>
__device__ __forceinline__ float4 conv_rowN(const WinT<NR>& win, const float* L,
                                            const float* Rv, const float* w, int j) {
    float4 a;
    const float4 v0 = win.r[j], v1 = win.r[j + 1], v2 = win.r[j + 2];
    a.x  = w[0]*L[j]   + w[1]*v0.x + w[2]*v0.y;
    a.y  = w[0]*v0.x   + w[1]*v0.y + w[2]*v0.z;
    a.z  = w[0]*v0.y   + w[1]*v0.z + w[2]*v0.w;
    a.w  = w[0]*v0.z   + w[1]*v0.w + w[2]*Rv[j];
    a.x += w[3]*L[j+1] + w[4]*v1.x + w[5]*v1.y;
    a.y += w[3]*v1.x   + w[4]*v1.y + w[5]*v1.z;
    a.z += w[3]*v1.y   + w[4]*v1.z + w[5]*v1.w;
    a.w += w[3]*v1.z   + w[4]*v1.w + w[5]*Rv[j+1];
    a.x += w[6]*L[j+2] + w[7]*v2.x + w[8]*v2.y;
    a.y += w[6]*v2.x   + w[7]*v2.y + w[8]*v2.z;
    a.z += w[6]*v2.y   + w[7]*v2.z + w[8]*v2.w;
    a.w += w[6]*v2.z   + w[7]*v2.w + w[8]*Rv[j+2];
    return a;
}

// ---------------- K3a: partial LN stats over half the channels -----------------
// block = (band, b, half). 256 threads / 8 warps x 16 channels.  (R6 config)
__global__ void __launch_bounds__(256, 3)
stats_kernel(const float* __restrict__ x) {
    __shared__ float s_w[128 * 9];
    __shared__ float s_sum[SWARP * SBPX];
    __shared__ float s_sq[SWARP * SBPX];

    const int tid  = threadIdx.x;
    const int warp = tid >> 5;
    const int lane = tid & 31;
    const int h0   = blockIdx.x * SBAND;
    const int b    = blockIdx.y;
    const int cg   = blockIdx.z;           // 0 or 1: channel half

    for (int i = tid; i < 128 * 9; i += 256) {
        const int gi = cg * 128 * 9 + i;
        s_w[i] = g_aggw[b * (C_ * 9) + gi] * g_gate[b * C_ + cg * 128 + i / 9];
    }
    __syncthreads();

    const int c0 = cg * 128 + warp * SCH;
    const float4* xb = reinterpret_cast<const float4*>(x + ((size_t)b * C_ + c0) * HW_);

    float4 psum[SBAND], psq[SBAND];
#pragma unroll
    for (int j = 0; j < SBAND; j++) {
        psum[j] = make_float4(0.f, 0.f, 0.f, 0.f);
        psq[j]  = make_float4(0.f, 0.f, 0.f, 0.f);
    }

    for (int ci = 0; ci < SCH; ci++) {
        WinT<6> win;
        load_winN<6>(xb + (size_t)ci * (HW_ / 4), h0, lane, win);
        float L[6], Rv[6];
        shiftsN<6>(win, L, Rv, lane);
        const float* wc = s_w + (warp * SCH + ci) * 9;
        float w[9];
#pragma unroll
        for (int i = 0; i < 9; i++) w[i] = wc[i];
#pragma unroll
        for (int j = 0; j < SBAND; j++) {
            float4 a = conv_rowN<6>(win, L, Rv, w, j);
            psum[j].x += a.x; psum[j].y += a.y; psum[j].z += a.z; psum[j].w += a.w;
            psq[j].x += a.x*a.x; psq[j].y += a.y*a.y; psq[j].z += a.z*a.z; psq[j].w += a.w*a.w;
        }
    }

#pragma unroll
    for (int j = 0; j < SBAND; j++) {
        const int px = j * W_ + lane * 4;
        *reinterpret_cast<float4*>(&s_sum[warp * SBPX + px]) = psum[j];
        *reinterpret_cast<float4*>(&s_sq[warp * SBPX + px])  = psq[j];
    }
    __syncthreads();

    for (int px = tid; px < SBPX; px += 256) {
        float s = 0.f, q = 0.f;
#pragma unroll
        for (int w = 0; w < SWARP; w++) {
            s += s_sum[w * SBPX + px];
            q += s_sq[w * SBPX + px];
        }
        const size_t o = (size_t)b * HW_ + h0 * W_ + px;
        g_ps[cg][o] = s;
        g_pq[cg][o] = q;
    }
}

// ---------------- K3b: conv recompute + LN + GELU + residual -------------------
// block = (band of 8 rows, b, channel-group of 8). 256 threads / 8 warps x 1 ch.
// LN stats combined from partials during staging (no separate combine kernel).
__global__ void __launch_bounds__(256, 2)
apply_kernel(const float* __restrict__ x, const float* __restrict__ gamma,
             const float* __restrict__ beta, float* __restrict__ out) {
    __shared__ float s_w[ACH * 9];
    __shared__ float s_g[ACH];
    __shared__ float s_b[ACH];
    __shared__ float s_mu[ABPX];
    __shared__ float s_rs[ABPX];

    const int tid  = threadIdx.x;
    const int warp = tid >> 5;
    const int lane = tid & 31;
    const int h0   = blockIdx.x * ABAND;
    const int b    = blockIdx.y;
    const int cz   = blockIdx.z * ACH;      // first channel of this block

    if (tid < ACH * 9)
        s_w[tid] = g_aggw[b * (C_ * 9) + cz * 9 + tid] * g_gate[b * C_ + cz + tid / 9];
    if (tid >= 96 && tid < 96 + ACH)   s_g[tid - 96]  = gamma[cz + tid - 96];
    if (tid >= 128 && tid < 128 + ACH) s_b[tid - 128] = beta[cz + tid - 128];
    // combine partial stats -> mu / rstd for this band (1024 px)
    for (int px = tid; px < ABPX; px += 256) {
        const size_t o = (size_t)b * HW_ + h0 * W_ + px;
        const float s = g_ps[0][o] + g_ps[1][o];
        const float q = g_pq[0][o] + g_pq[1][o];
        const float mu  = s * (1.0f / (float)C_);
        const float var = q * (1.0f / (float)C_) - mu * mu;
        s_mu[px] = mu;
        s_rs[px] = rsqrtf(var + 1e-6f);
    }
    __syncthreads();

    const int c = cz + warp;
    const float4* xb = reinterpret_cast<const float4*>(x + ((size_t)b * C_ + c) * HW_);
    float4* ob = reinterpret_cast<float4*>(out + ((size_t)b * C_ + c) * HW_);

    WinT<10> win;
    load_winN<10>(xb, h0, lane, win);
    float L[10], Rv[10];
    shiftsN<10>(win, L, Rv, lane);
    float w[9];
#pragma unroll
    for (int i = 0; i < 9; i++) w[i] = s_w[warp * 9 + i];
    const float gm = s_g[warp];
    const float bt = s_b[warp];

#pragma unroll
    for (int j = 0; j < ABAND; j++) {
        float4 a = conv_rowN<10>(win, L, Rv, w, j);
        const float4 mu4 = *reinterpret_cast<const float4*>(&s_mu[j * W_ + lane * 4]);
        const float4 rs4 = *reinterpret_cast<const float4*>(&s_rs[j * W_ + lane * 4]);
        const float4 res = win.r[j + 1];            // center row == residual x
        float4 o;
        o.x = gelu_f((a.x - mu4.x) * rs4.x * gm + bt) + res.x;
        o.y = gelu_f((a.y - mu4.y) * rs4.y * gm + bt) + res.y;
        o.z = gelu_f((a.z - mu4.z) * rs4.z * gm + bt) + res.z;
        o.w = gelu_f((a.w - mu4.w) * rs4.w * gm + bt) + res.w;
        ob[(size_t)(h0 + j) * (W_ / 4) + lane] = o;
    }
}

// ---------------- launcher -----------------------------------------------------
extern "C" void kernel_launch(void* const* d_in, const int* in_sizes, int n_in,
                              void* d_out, int out_size) {
    const float* x     = (const float*)d_in[0];
    const float* w1    = (const float*)d_in[1];
    const float* b1    = (const float*)d_in[2];
    const float* w2    = (const float*)d_in[3];
    const float* b2    = (const float*)d_in[4];
    const float* kw    = (const float*)d_in[5];
    const float* eca   = (const float*)d_in[6];
    const float* gamma = (const float*)d_in[7];
    const float* beta  = (const float*)d_in[8];
    float* out = (float*)d_out;

    gap_kernel<<<B_ * C_, 256>>>(x);
    attn_kernel<<<B_, 256>>>(w1, b1, w2, b2, kw, eca);
    dim3 sgrid(H_ / SBAND, B_, 2);
    stats_kernel<<<sgrid, 256>>>(x);
    dim3 agrid(H_ / ABAND, B_, C_ / ACH);
    apply_kernel<<<agrid, 256>>>(x, gamma, beta, out);
}

// round 8
// speedup vs baseline: 1.2271x; 1.2271x over previous
#include <cuda_runtime.h>
#include <cuda_bf16.h>
#include <math.h>

#define B_  16
#define C_  256
#define H_  128
#define W_  128
#define K_  12
#define HW_ (H_ * W_)

#define SBAND 4                   // stats: rows per band
#define SBPX  (SBAND * W_)        // 512
#define SWARP 8                   // warps per stats block
#define SCH   16                  // channels per stats warp

#define ABAND 4                   // apply: rows per band
#define ABPX  (ABAND * W_)        // 512
#define ACH   8                   // channels per apply block (1 per warp)

// ---------------- device scratch ----------------------------------------------
__device__ float g_y[B_ * C_];
__device__ float g_gate[B_ * C_];
__device__ float g_aggw[B_ * C_ * 9];
__device__ float g_ps[2][B_ * HW_];   // partial sum   (per channel-half)
__device__ float g_pq[2][B_ * HW_];   // partial sumsq

__device__ __forceinline__ float sigmoidf_(float v) {
    return 1.0f / (1.0f + __expf(-v));
}

// Branchless erf (Abramowitz-Stegun 7.1.26): |abs err| <= 1.5e-7, no divergence.
__device__ __forceinline__ float erf_branchless(float v) {
    const float t = fabsf(v);
    const float k = __frcp_rn(fmaf(0.3275911f, t, 1.0f));
    float p =            1.061405429f;
    p = fmaf(p, k, -1.453152027f);
    p = fmaf(p, k,  1.421413741f);
    p = fmaf(p, k, -0.284496736f);
    p = fmaf(p, k,  0.254829592f);
    p = p * k;
    const float e = __expf(-t * t);
    const float r = fmaf(-p, e, 1.0f);
    return copysignf(r, v);
}
__device__ __forceinline__ float gelu_f(float v) {
    return 0.5f * v * (1.0f + erf_branchless(v * 0.70710678118654752f));
}

// ---------------- K1: global average pool per (b,c) ---------------------------
__global__ void gap_kernel(const float* __restrict__ x) {
    __shared__ float red[8];
    const int bc = blockIdx.x;
    const float4* xp = reinterpret_cast<const float4*>(x + (size_t)bc * HW_);
    float s = 0.f;
#pragma unroll
    for (int i = 0; i < 16; i++) {
        float4 v = xp[threadIdx.x + 256 * i];
        s += (v.x + v.y) + (v.z + v.w);
    }
#pragma unroll
    for (int o = 16; o; o >>= 1) s += __shfl_xor_sync(0xffffffffu, s, o);
    if ((threadIdx.x & 31) == 0) red[threadIdx.x >> 5] = s;
    __syncthreads();
    if (threadIdx.x < 8) {
        s = red[threadIdx.x];
#pragma unroll
        for (int o = 4; o; o >>= 1) s += __shfl_xor_sync(0x000000ffu, s, o);
        if (threadIdx.x == 0) g_y[bc] = s * (1.0f / (float)HW_);
    }
}

// ---------------- K2: ECA gate + MLP + softmax + kernel aggregation -----------
__global__ void attn_kernel(const float* __restrict__ w1, const float* __restrict__ b1,
                            const float* __restrict__ w2, const float* __restrict__ b2,
                            const float* __restrict__ kw, const float* __restrict__ eca) {
    const int b = blockIdx.x;
    const int t = threadIdx.x;
    __shared__ float ysm[C_ + 2];
    __shared__ float psm[C_];
    __shared__ float hsm[C_];
    __shared__ float lsm[K_];
    __shared__ float alph[K_];

    ysm[t + 1] = g_y[b * C_ + t];
    if (t == 0) { ysm[0] = 0.f; ysm[C_ + 1] = 0.f; }
    __syncthreads();

    const float e0 = eca[0], e1 = eca[1], e2 = eca[2];
    float gate = sigmoidf_(e0 * ysm[t] + e1 * ysm[t + 1] + e2 * ysm[t + 2]);
    g_gate[b * C_ + t] = gate;
    psm[t] = gate * ysm[t + 1];
    __syncthreads();

    float acc = b1[t];
    for (int c = 0; c < C_; c++) acc += psm[c] * w1[c * C_ + t];
    hsm[t] = 0.5f * acc * (1.0f + erff(acc * 0.70710678118654752f));
    __syncthreads();

    if (t < K_) {
        float l = b2[t];
        for (int c = 0; c < C_; c++) l += hsm[c] * w2[c * K_ + t];
        lsm[t] = l;
    }
    __syncthreads();

    if (t == 0) {
        float m = lsm[0];
#pragma unroll
        for (int k = 1; k < K_; k++) m = fmaxf(m, lsm[k]);
        float s = 0.f;
#pragma unroll
        for (int k = 0; k < K_; k++) { float e = __expf(lsm[k] - m); alph[k] = e; s += e; }
        float inv = 1.0f / s;
#pragma unroll
        for (int k = 0; k < K_; k++) alph[k] *= inv;
    }
    __syncthreads();

    for (int idx = t; idx < C_ * 9; idx += 256) {
        float v = 0.f;
#pragma unroll
        for (int k = 0; k < K_; k++) v += alph[k] * kw[k * (C_ * 9) + idx];
        g_aggw[b * (C_ * 9) + idx] = v;
    }
}

// ---------------- register sliding-window conv helpers -------------------------
template <int NR> struct WinT { float4 r[NR]; };

template <int NR>
__device__ __forceinline__ void load_winN(const float4* __restrict__ xc4,
                                          int h0, int lane, WinT<NR>& w) {
#pragma unroll
    for (int r = 0; r < NR; r++) {
        const int gh = h0 - 1 + r;
        if (gh >= 0 && gh < H_) w.r[r] = xc4[gh * (W_ / 4) + lane];
        else                    w.r[r] = make_float4(0.f, 0.f, 0.f, 0.f);
    }
}

template <int NR>
__device__ __forceinline__ void shiftsN(const WinT<NR>& win, float* L, float* Rv, int lane) {
#pragma unroll
    for (int r = 0; r < NR; r++) {
        float l  = __shfl_up_sync(0xffffffffu, win.r[r].w, 1);
        float rr = __shfl_down_sync(0xffffffffu, win.r[r].x, 1);
        L[r]  = (lane == 0)  ? 0.f : l;
        Rv[r] = (lane == 31) ? 0.f : rr;
    }
}

template <int NR>
__device__ __forceinline__ float4 conv_rowN(const WinT<NR>& win, const float* L,
                                            const float* Rv, const float* w, int j) {
    float4 a;
    const float4 v0 = win.r[j], v1 = win.r[j + 1], v2 = win.r[j + 2];
    a.x  = w[0]*L[j]   + w[1]*v0.x + w[2]*v0.y;
    a.y  = w[0]*v0.x   + w[1]*v0.y + w[2]*v0.z;
    a.z  = w[0]*v0.y   + w[1]*v0.z + w[2]*v0.w;
    a.w  = w[0]*v0.z   + w[1]*v0.w + w[2]*Rv[j];
    a.x += w[3]*L[j+1] + w[4]*v1.x + w[5]*v1.y;
    a.y += w[3]*v1.x   + w[4]*v1.y + w[5]*v1.z;
    a.z += w[3]*v1.y   + w[4]*v1.z + w[5]*v1.w;
    a.w += w[3]*v1.z   + w[4]*v1.w + w[5]*Rv[j+1];
    a.x += w[6]*L[j+2] + w[7]*v2.x + w[8]*v2.y;
    a.y += w[6]*v2.x   + w[7]*v2.y + w[8]*v2.z;
    a.z += w[6]*v2.y   + w[7]*v2.z + w[8]*v2.w;
    a.w += w[6]*v2.z   + w[7]*v2.w + w[8]*Rv[j+2];
    return a;
}

// ---------------- K3a: partial LN stats over half the channels -----------------
// block = (band, b, half). 256 threads / 8 warps x 16 channels.  (R6 config)
__global__ void __launch_bounds__(256, 3)
stats_kernel(const float* __restrict__ x) {
    __shared__ float s_w[128 * 9];
    __shared__ float s_sum[SWARP * SBPX];
    __shared__ float s_sq[SWARP * SBPX];

    const int tid  = threadIdx.x;
    const int warp = tid >> 5;
    const int lane = tid & 31;
    const int h0   = blockIdx.x * SBAND;
    const int b    = blockIdx.y;
    const int cg   = blockIdx.z;           // 0 or 1: channel half

    for (int i = tid; i < 128 * 9; i += 256) {
        const int gi = cg * 128 * 9 + i;
        s_w[i] = g_aggw[b * (C_ * 9) + gi] * g_gate[b * C_ + cg * 128 + i / 9];
    }
    __syncthreads();

    const int c0 = cg * 128 + warp * SCH;
    const float4* xb = reinterpret_cast<const float4*>(x + ((size_t)b * C_ + c0) * HW_);

    float4 psum[SBAND], psq[SBAND];
#pragma unroll
    for (int j = 0; j < SBAND; j++) {
        psum[j] = make_float4(0.f, 0.f, 0.f, 0.f);
        psq[j]  = make_float4(0.f, 0.f, 0.f, 0.f);
    }

    for (int ci = 0; ci < SCH; ci++) {
        WinT<6> win;
        load_winN<6>(xb + (size_t)ci * (HW_ / 4), h0, lane, win);
        float L[6], Rv[6];
        shiftsN<6>(win, L, Rv, lane);
        const float* wc = s_w + (warp * SCH + ci) * 9;
        float w[9];
#pragma unroll
        for (int i = 0; i < 9; i++) w[i] = wc[i];
#pragma unroll
        for (int j = 0; j < SBAND; j++) {
            float4 a = conv_rowN<6>(win, L, Rv, w, j);
            psum[j].x += a.x; psum[j].y += a.y; psum[j].z += a.z; psum[j].w += a.w;
            psq[j].x += a.x*a.x; psq[j].y += a.y*a.y; psq[j].z += a.z*a.z; psq[j].w += a.w*a.w;
        }
    }

#pragma unroll
    for (int j = 0; j < SBAND; j++) {
        const int px = j * W_ + lane * 4;
        *reinterpret_cast<float4*>(&s_sum[warp * SBPX + px]) = psum[j];
        *reinterpret_cast<float4*>(&s_sq[warp * SBPX + px])  = psq[j];
    }
    __syncthreads();

    for (int px = tid; px < SBPX; px += 256) {
        float s = 0.f, q = 0.f;
#pragma unroll
        for (int w = 0; w < SWARP; w++) {
            s += s_sum[w * SBPX + px];
            q += s_sq[w * SBPX + px];
        }
        const size_t o = (size_t)b * HW_ + h0 * W_ + px;
        g_ps[cg][o] = s;
        g_pq[cg][o] = q;
    }
}

// ---------------- K3b: conv recompute + LN + GELU + residual -------------------
// block = (band of 4 rows, b, channel-group of 8). 256 threads / 8 warps x 1 ch.
// LN stats combined from partials during staging. 4 CTAs/SM target (<=64 regs).
__global__ void __launch_bounds__(256, 4)
apply_kernel(const float* __restrict__ x, const float* __restrict__ gamma,
             const float* __restrict__ beta, float* __restrict__ out) {
    __shared__ float s_w[ACH * 9];
    __shared__ float s_g[ACH];
    __shared__ float s_b[ACH];
    __shared__ float s_mu[ABPX];
    __shared__ float s_rs[ABPX];

    const int tid  = threadIdx.x;
    const int warp = tid >> 5;
    const int lane = tid & 31;
    const int h0   = blockIdx.x * ABAND;
    const int b    = blockIdx.y;
    const int cz   = blockIdx.z * ACH;      // first channel of this block

    if (tid < ACH * 9)
        s_w[tid] = g_aggw[b * (C_ * 9) + cz * 9 + tid] * g_gate[b * C_ + cz + tid / 9];
    if (tid >= 96 && tid < 96 + ACH)   s_g[tid - 96]  = gamma[cz + tid - 96];
    if (tid >= 128 && tid < 128 + ACH) s_b[tid - 128] = beta[cz + tid - 128];
    // combine partial stats -> mu / rstd for this band (512 px)
    for (int px = tid; px < ABPX; px += 256) {
        const size_t o = (size_t)b * HW_ + h0 * W_ + px;
        const float s = g_ps[0][o] + g_ps[1][o];
        const float q = g_pq[0][o] + g_pq[1][o];
        const float mu  = s * (1.0f / (float)C_);
        const float var = q * (1.0f / (float)C_) - mu * mu;
        s_mu[px] = mu;
        s_rs[px] = rsqrtf(var + 1e-6f);
    }
    __syncthreads();

    const int c = cz + warp;
    const float4* xb = reinterpret_cast<const float4*>(x + ((size_t)b * C_ + c) * HW_);
    float4* ob = reinterpret_cast<float4*>(out + ((size_t)b * C_ + c) * HW_);

    WinT<6> win;
    load_winN<6>(xb, h0, lane, win);
    float L[6], Rv[6];
    shiftsN<6>(win, L, Rv, lane);
    float w[9];
#pragma unroll
    for (int i = 0; i < 9; i++) w[i] = s_w[warp * 9 + i];
    const float gm = s_g[warp];
    const float bt = s_b[warp];

#pragma unroll
    for (int j = 0; j < ABAND; j++) {
        float4 a = conv_rowN<6>(win, L, Rv, w, j);
        const float4 mu4 = *reinterpret_cast<const float4*>(&s_mu[j * W_ + lane * 4]);
        const float4 rs4 = *reinterpret_cast<const float4*>(&s_rs[j * W_ + lane * 4]);
        const float4 res = win.r[j + 1];            // center row == residual x
        float4 o;
        o.x = gelu_f((a.x - mu4.x) * rs4.x * gm + bt) + res.x;
        o.y = gelu_f((a.y - mu4.y) * rs4.y * gm + bt) + res.y;
        o.z = gelu_f((a.z - mu4.z) * rs4.z * gm + bt) + res.z;
        o.w = gelu_f((a.w - mu4.w) * rs4.w * gm + bt) + res.w;
        ob[(size_t)(h0 + j) * (W_ / 4) + lane] = o;
    }
}

// ---------------- launcher -----------------------------------------------------
extern "C" void kernel_launch(void* const* d_in, const int* in_sizes, int n_in,
                              void* d_out, int out_size) {
    const float* x     = (const float*)d_in[0];
    const float* w1    = (const float*)d_in[1];
    const float* b1    = (const float*)d_in[2];
    const float* w2    = (const float*)d_in[3];
    const float* b2    = (const float*)d_in[4];
    const float* kw    = (const float*)d_in[5];
    const float* eca   = (const float*)d_in[6];
    const float* gamma = (const float*)d_in[7];
    const float* beta  = (const float*)d_in[8];
    float* out = (float*)d_out;

    gap_kernel<<<B_ * C_, 256>>>(x);
    attn_kernel<<<B_, 256>>>(w1, b1, w2, b2, kw, eca);
    dim3 sgrid(H_ / SBAND, B_, 2);
    stats_kernel<<<sgrid, 256>>>(x);
    dim3 agrid(H_ / ABAND, B_, C_ / ACH);
    apply_kernel<<<agrid, 256>>>(x, gamma, beta, out);
}

// round 9
// speedup vs baseline: 1.2328x; 1.0046x over previous
#include <cuda_runtime.h>
#include <cuda_bf16.h>
#include <math.h>

#define B_  16
#define C_  256
#define H_  128
#define W_  128
#define K_  12
#define HW_ (H_ * W_)

#define SBAND 4                   // stats: rows per band
#define SBPX  (SBAND * W_)        // 512
#define SWARP 8                   // warps per stats block
#define SCH   16                  // channels per stats warp

#define ABAND 4                   // apply: rows per band
#define ABPX  (ABAND * W_)        // 512
#define ACH   8                   // channels per apply block (1 per warp)

typedef unsigned long long u64;

// ---------------- device scratch ----------------------------------------------
__device__ float g_y[B_ * C_];
__device__ float g_gate[B_ * C_];
__device__ float g_aggw[B_ * C_ * 9];
__device__ float g_ps[2][B_ * HW_];   // partial sum   (per channel-half)
__device__ float g_pq[2][B_ * HW_];   // partial sumsq

__device__ __forceinline__ float sigmoidf_(float v) {
    return 1.0f / (1.0f + __expf(-v));
}

// Branchless erf (Abramowitz-Stegun 7.1.26): |abs err| <= 1.5e-7, no divergence.
__device__ __forceinline__ float erf_branchless(float v) {
    const float t = fabsf(v);
    const float k = __frcp_rn(fmaf(0.3275911f, t, 1.0f));
    float p =            1.061405429f;
    p = fmaf(p, k, -1.453152027f);
    p = fmaf(p, k,  1.421413741f);
    p = fmaf(p, k, -0.284496736f);
    p = fmaf(p, k,  0.254829592f);
    p = p * k;
    const float e = __expf(-t * t);
    const float r = fmaf(-p, e, 1.0f);
    return copysignf(r, v);
}
__device__ __forceinline__ float gelu_f(float v) {
    return 0.5f * v * (1.0f + erf_branchless(v * 0.70710678118654752f));
}

// ---------------- packed f32x2 helpers ------------------------------------------
__device__ __forceinline__ u64 pk2(float lo, float hi) {
    u64 r;
    asm("mov.b64 %0, {%1, %2};" : "=l"(r)
        : "r"(__float_as_uint(lo)), "r"(__float_as_uint(hi)));
    return r;
}
__device__ __forceinline__ float2 up2(u64 v) {
    unsigned int lo, hi;
    asm("mov.b64 {%0, %1}, %2;" : "=r"(lo), "=r"(hi) : "l"(v));
    return make_float2(__uint_as_float(lo), __uint_as_float(hi));
}
__device__ __forceinline__ u64 f2fma(u64 a, u64 b, u64 c) {
    u64 d;
    asm("fma.rn.f32x2 %0, %1, %2, %3;" : "=l"(d) : "l"(a), "l"(b), "l"(c));
    return d;
}
__device__ __forceinline__ u64 f2mul(u64 a, u64 b) {
    u64 d;
    asm("mul.rn.f32x2 %0, %1, %2;" : "=l"(d) : "l"(a), "l"(b));
    return d;
}
__device__ __forceinline__ u64 f2add(u64 a, u64 b) {
    u64 d;
    asm("add.rn.f32x2 %0, %1, %2;" : "=l"(d) : "l"(a), "l"(b));
    return d;
}

// ---------------- K1: global average pool per (b,c) ---------------------------
__global__ void gap_kernel(const float* __restrict__ x) {
    __shared__ float red[8];
    const int bc = blockIdx.x;
    const float4* xp = reinterpret_cast<const float4*>(x + (size_t)bc * HW_);
    float s = 0.f;
#pragma unroll
    for (int i = 0; i < 16; i++) {
        float4 v = xp[threadIdx.x + 256 * i];
        s += (v.x + v.y) + (v.z + v.w);
    }
#pragma unroll
    for (int o = 16; o; o >>= 1) s += __shfl_xor_sync(0xffffffffu, s, o);
    if ((threadIdx.x & 31) == 0) red[threadIdx.x >> 5] = s;
    __syncthreads();
    if (threadIdx.x < 8) {
        s = red[threadIdx.x];
#pragma unroll
        for (int o = 4; o; o >>= 1) s += __shfl_xor_sync(0x000000ffu, s, o);
        if (threadIdx.x == 0) g_y[bc] = s * (1.0f / (float)HW_);
    }
}

// ---------------- K2: ECA gate + MLP + softmax + kernel aggregation -----------
__global__ void attn_kernel(const float* __restrict__ w1, const float* __restrict__ b1,
                            const float* __restrict__ w2, const float* __restrict__ b2,
                            const float* __restrict__ kw, const float* __restrict__ eca) {
    const int b = blockIdx.x;
    const int t = threadIdx.x;
    __shared__ float ysm[C_ + 2];
    __shared__ float psm[C_];
    __shared__ float hsm[C_];
    __shared__ float lsm[K_];
    __shared__ float alph[K_];

    ysm[t + 1] = g_y[b * C_ + t];
    if (t == 0) { ysm[0] = 0.f; ysm[C_ + 1] = 0.f; }
    __syncthreads();

    const float e0 = eca[0], e1 = eca[1], e2 = eca[2];
    float gate = sigmoidf_(e0 * ysm[t] + e1 * ysm[t + 1] + e2 * ysm[t + 2]);
    g_gate[b * C_ + t] = gate;
    psm[t] = gate * ysm[t + 1];
    __syncthreads();

    float acc = b1[t];
    for (int c = 0; c < C_; c++) acc += psm[c] * w1[c * C_ + t];
    hsm[t] = 0.5f * acc * (1.0f + erff(acc * 0.70710678118654752f));
    __syncthreads();

    if (t < K_) {
        float l = b2[t];
        for (int c = 0; c < C_; c++) l += hsm[c] * w2[c * K_ + t];
        lsm[t] = l;
    }
    __syncthreads();

    if (t == 0) {
        float m = lsm[0];
#pragma unroll
        for (int k = 1; k < K_; k++) m = fmaxf(m, lsm[k]);
        float s = 0.f;
#pragma unroll
        for (int k = 0; k < K_; k++) { float e = __expf(lsm[k] - m); alph[k] = e; s += e; }
        float inv = 1.0f / s;
#pragma unroll
        for (int k = 0; k < K_; k++) alph[k] *= inv;
    }
    __syncthreads();

    for (int idx = t; idx < C_ * 9; idx += 256) {
        float v = 0.f;
#pragma unroll
        for (int k = 0; k < K_; k++) v += alph[k] * kw[k * (C_ * 9) + idx];
        g_aggw[b * (C_ * 9) + idx] = v;
    }
}

// ---------------- scalar sliding-window helpers (apply kernel) -----------------
template <int NR> struct WinT { float4 r[NR]; };

template <int NR>
__device__ __forceinline__ void load_winN(const float4* __restrict__ xc4,
                                          int h0, int lane, WinT<NR>& w) {
#pragma unroll
    for (int r = 0; r < NR; r++) {
        const int gh = h0 - 1 + r;
        if (gh >= 0 && gh < H_) w.r[r] = xc4[gh * (W_ / 4) + lane];
        else                    w.r[r] = make_float4(0.f, 0.f, 0.f, 0.f);
    }
}

template <int NR>
__device__ __forceinline__ void shiftsN(const WinT<NR>& win, float* L, float* Rv, int lane) {
#pragma unroll
    for (int r = 0; r < NR; r++) {
        float l  = __shfl_up_sync(0xffffffffu, win.r[r].w, 1);
        float rr = __shfl_down_sync(0xffffffffu, win.r[r].x, 1);
        L[r]  = (lane == 0)  ? 0.f : l;
        Rv[r] = (lane == 31) ? 0.f : rr;
    }
}

template <int NR>
__device__ __forceinline__ float4 conv_rowN(const WinT<NR>& win, const float* L,
                                            const float* Rv, const float* w, int j) {
    float4 a;
    const float4 v0 = win.r[j], v1 = win.r[j + 1], v2 = win.r[j + 2];
    a.x  = w[0]*L[j]   + w[1]*v0.x + w[2]*v0.y;
    a.y  = w[0]*v0.x   + w[1]*v0.y + w[2]*v0.z;
    a.z  = w[0]*v0.y   + w[1]*v0.z + w[2]*v0.w;
    a.w  = w[0]*v0.z   + w[1]*v0.w + w[2]*Rv[j];
    a.x += w[3]*L[j+1] + w[4]*v1.x + w[5]*v1.y;
    a.y += w[3]*v1.x   + w[4]*v1.y + w[5]*v1.z;
    a.z += w[3]*v1.y   + w[4]*v1.z + w[5]*v1.w;
    a.w += w[3]*v1.z   + w[4]*v1.w + w[5]*Rv[j+1];
    a.x += w[6]*L[j+2] + w[7]*v2.x + w[8]*v2.y;
    a.y += w[6]*v2.x   + w[7]*v2.y + w[8]*v2.z;
    a.z += w[6]*v2.y   + w[7]*v2.z + w[8]*v2.w;
    a.w += w[6]*v2.z   + w[7]*v2.w + w[8]*Rv[j+2];
    return a;
}

// ---------------- packed row representation (stats kernel) ---------------------
struct PRow { u64 n0, n1, s0, s1, s2; };

__device__ __forceinline__ PRow make_prow(float4 v, int lane) {
    float l  = __shfl_up_sync(0xffffffffu, v.w, 1);
    float r  = __shfl_down_sync(0xffffffffu, v.x, 1);
    if (lane == 0)  l = 0.f;
    if (lane == 31) r = 0.f;
    PRow p;
    p.n0 = pk2(v.x, v.y);
    p.n1 = pk2(v.z, v.w);
    p.s0 = pk2(l,   v.x);
    p.s1 = pk2(v.y, v.z);
    p.s2 = pk2(v.w, r);
    return p;
}

// packed 3x3 conv: A = outputs (x,y), B = outputs (z,w) of one row of 4
__device__ __forceinline__ void conv_pairP(const PRow& p0, const PRow& p1, const PRow& p2,
                                           const u64* wp, u64& A, u64& B) {
    u64 a = f2mul(wp[0], p0.s0);
    a = f2fma(wp[1], p0.n0, a);
    a = f2fma(wp[2], p0.s1, a);
    a = f2fma(wp[3], p1.s0, a);
    a = f2fma(wp[4], p1.n0, a);
    a = f2fma(wp[5], p1.s1, a);
    a = f2fma(wp[6], p2.s0, a);
    a = f2fma(wp[7], p2.n0, a);
    a = f2fma(wp[8], p2.s1, a);
    u64 b = f2mul(wp[0], p0.s1);
    b = f2fma(wp[1], p0.n1, b);
    b = f2fma(wp[2], p0.s2, b);
    b = f2fma(wp[3], p1.s1, b);
    b = f2fma(wp[4], p1.n1, b);
    b = f2fma(wp[5], p1.s2, b);
    b = f2fma(wp[6], p2.s1, b);
    b = f2fma(wp[7], p2.n1, b);
    b = f2fma(wp[8], p2.s2, b);
    A = a; B = b;
}

// ---------------- K3a: partial LN stats over half the channels -----------------
// block = (half, b, band). 256 threads / 8 warps x 16 channels. f32x2 packed conv.
// band is the SLOWEST grid dim -> adjacent bands adjacent in time -> L2 halo reuse.
__global__ void __launch_bounds__(256, 2)
stats_kernel(const float* __restrict__ x) {
    __shared__ float s_w[128 * 9];
    __shared__ float s_sum[SWARP * SBPX];
    __shared__ float s_sq[SWARP * SBPX];

    const int tid  = threadIdx.x;
    const int warp = tid >> 5;
    const int lane = tid & 31;
    const int cg   = blockIdx.x;           // 0 or 1: channel half
    const int b    = blockIdx.y;
    const int h0   = blockIdx.z * SBAND;

    for (int i = tid; i < 128 * 9; i += 256) {
        const int gi = cg * 128 * 9 + i;
        s_w[i] = g_aggw[b * (C_ * 9) + gi] * g_gate[b * C_ + cg * 128 + i / 9];
    }
    __syncthreads();

    const int c0 = cg * 128 + warp * SCH;
    const float4* xb = reinterpret_cast<const float4*>(x + ((size_t)b * C_ + c0) * HW_);

    u64 sA[SBAND], sB[SBAND], qA[SBAND], qB[SBAND];
#pragma unroll
    for (int j = 0; j < SBAND; j++) { sA[j] = 0ull; sB[j] = 0ull; qA[j] = 0ull; qB[j] = 0ull; }

    for (int ci = 0; ci < SCH; ci++) {
        const float4* xc = xb + (size_t)ci * (HW_ / 4);
        float4 v[6];
#pragma unroll
        for (int r = 0; r < 6; r++) {
            const int gh = h0 - 1 + r;
            if (gh >= 0 && gh < H_) v[r] = xc[gh * (W_ / 4) + lane];
            else                    v[r] = make_float4(0.f, 0.f, 0.f, 0.f);
        }
        const float* wc = s_w + (warp * SCH + ci) * 9;
        u64 wp[9];
#pragma unroll
        for (int i = 0; i < 9; i++) { const float w = wc[i]; wp[i] = pk2(w, w); }

        u64 A, Bv;
        PRow p0 = make_prow(v[0], lane);
        PRow p1 = make_prow(v[1], lane);
        PRow p2 = make_prow(v[2], lane);
        conv_pairP(p0, p1, p2, wp, A, Bv);
        sA[0] = f2add(sA[0], A);  qA[0] = f2fma(A, A, qA[0]);
        sB[0] = f2add(sB[0], Bv); qB[0] = f2fma(Bv, Bv, qB[0]);

        p0 = make_prow(v[3], lane);
        conv_pairP(p1, p2, p0, wp, A, Bv);
        sA[1] = f2add(sA[1], A);  qA[1] = f2fma(A, A, qA[1]);
        sB[1] = f2add(sB[1], Bv); qB[1] = f2fma(Bv, Bv, qB[1]);

        p1 = make_prow(v[4], lane);
        conv_pairP(p2, p0, p1, wp, A, Bv);
        sA[2] = f2add(sA[2], A);  qA[2] = f2fma(A, A, qA[2]);
        sB[2] = f2add(sB[2], Bv); qB[2] = f2fma(Bv, Bv, qB[2]);

        p2 = make_prow(v[5], lane);
        conv_pairP(p0, p1, p2, wp, A, Bv);
        sA[3] = f2add(sA[3], A);  qA[3] = f2fma(A, A, qA[3]);
        sB[3] = f2add(sB[3], Bv); qB[3] = f2fma(Bv, Bv, qB[3]);
    }

#pragma unroll
    for (int j = 0; j < SBAND; j++) {
        const int px = j * W_ + lane * 4;
        const float2 a0 = up2(sA[j]), b0 = up2(sB[j]);
        const float2 a1 = up2(qA[j]), b1 = up2(qB[j]);
        *reinterpret_cast<float4*>(&s_sum[warp * SBPX + px]) = make_float4(a0.x, a0.y, b0.x, b0.y);
        *reinterpret_cast<float4*>(&s_sq[warp * SBPX + px])  = make_float4(a1.x, a1.y, b1.x, b1.y);
    }
    __syncthreads();

    for (int px = tid; px < SBPX; px += 256) {
        float s = 0.f, q = 0.f;
#pragma unroll
        for (int w = 0; w < SWARP; w++) {
            s += s_sum[w * SBPX + px];
            q += s_sq[w * SBPX + px];
        }
        const size_t o = (size_t)b * HW_ + h0 * W_ + px;
        g_ps[cg][o] = s;
        g_pq[cg][o] = q;
    }
}

// ---------------- K3b: conv recompute + LN + GELU + residual -------------------
// block = (channel-group, b, band). 256 threads / 8 warps x 1 channel.
// band slowest -> L2 halo reuse. LN stats combined from partials during staging.
__global__ void __launch_bounds__(256, 4)
apply_kernel(const float* __restrict__ x, const float* __restrict__ gamma,
             const float* __restrict__ beta, float* __restrict__ out) {
    __shared__ float s_w[ACH * 9];
    __shared__ float s_g[ACH];
    __shared__ float s_b[ACH];
    __shared__ float s_mu[ABPX];
    __shared__ float s_rs[ABPX];

    const int tid  = threadIdx.x;
    const int warp = tid >> 5;
    const int lane = tid & 31;
    const int cz   = blockIdx.x * ACH;      // first channel of this block
    const int b    = blockIdx.y;
    const int h0   = blockIdx.z * ABAND;

    if (tid < ACH * 9)
        s_w[tid] = g_aggw[b * (C_ * 9) + cz * 9 + tid] * g_gate[b * C_ + cz + tid / 9];
    if (tid >= 96 && tid < 96 + ACH)   s_g[tid - 96]  = gamma[cz + tid - 96];
    if (tid >= 128 && tid < 128 + ACH) s_b[tid - 128] = beta[cz + tid - 128];
    // combine partial stats -> mu / rstd for this band (512 px)
    for (int px = tid; px < ABPX; px += 256) {
        const size_t o = (size_t)b * HW_ + h0 * W_ + px;
        const float s = g_ps[0][o] + g_ps[1][o];
        const float q = g_pq[0][o] + g_pq[1][o];
        const float mu  = s * (1.0f / (float)C_);
        const float var = q * (1.0f / (float)C_) - mu * mu;
        s_mu[px] = mu;
        s_rs[px] = rsqrtf(var + 1e-6f);
    }
    __syncthreads();

    const int c = cz + warp;
    const float4* xb = reinterpret_cast<const float4*>(x + ((size_t)b * C_ + c) * HW_);
    float4* ob = reinterpret_cast<float4*>(out + ((size_t)b * C_ + c) * HW_);

    WinT<6> win;
    load_winN<6>(xb, h0, lane, win);
    float L[6], Rv[6];
    shiftsN<6>(win, L, Rv, lane);
    float w[9];
#pragma unroll
    for (int i = 0; i < 9; i++) w[i] = s_w[warp * 9 + i];
    const float gm = s_g[warp];
    const float bt = s_b[warp];

#pragma unroll
    for (int j = 0; j < ABAND; j++) {
        float4 a = conv_rowN<6>(win, L, Rv, w, j);
        const float4 mu4 = *reinterpret_cast<const float4*>(&s_mu[j * W_ + lane * 4]);
        const float4 rs4 = *reinterpret_cast<const float4*>(&s_rs[j * W_ + lane * 4]);
        const float4 res = win.r[j + 1];            // center row == residual x
        float4 o;
        o.x = gelu_f((a.x - mu4.x) * rs4.x * gm + bt) + res.x;
        o.y = gelu_f((a.y - mu4.y) * rs4.y * gm + bt) + res.y;
        o.z = gelu_f((a.z - mu4.z) * rs4.z * gm + bt) + res.z;
        o.w = gelu_f((a.w - mu4.w) * rs4.w * gm + bt) + res.w;
        ob[(size_t)(h0 + j) * (W_ / 4) + lane] = o;
    }
}

// ---------------- launcher -----------------------------------------------------
extern "C" void kernel_launch(void* const* d_in, const int* in_sizes, int n_in,
                              void* d_out, int out_size) {
    const float* x     = (const float*)d_in[0];
    const float* w1    = (const float*)d_in[1];
    const float* b1    = (const float*)d_in[2];
    const float* w2    = (const float*)d_in[3];
    const float* b2    = (const float*)d_in[4];
    const float* kw    = (const float*)d_in[5];
    const float* eca   = (const float*)d_in[6];
    const float* gamma = (const float*)d_in[7];
    const float* beta  = (const float*)d_in[8];
    float* out = (float*)d_out;

    gap_kernel<<<B_ * C_, 256>>>(x);
    attn_kernel<<<B_, 256>>>(w1, b1, w2, b2, kw, eca);
    dim3 sgrid(2, B_, H_ / SBAND);
    stats_kernel<<<sgrid, 256>>>(x);
    dim3 agrid(C_ / ACH, B_, H_ / ABAND);
    apply_kernel<<<agrid, 256>>>(x, gamma, beta, out);
}

// round 10
// speedup vs baseline: 1.4120x; 1.1454x over previous
#include <cuda_runtime.h>
#include <cuda_bf16.h>
#include <math.h>

#define B_  16
#define C_  256
#define H_  128
#define W_  128
#define K_  12
#define HW_ (H_ * W_)

#define SBAND 4                   // stats: rows per band
#define SBPX  (SBAND * W_)        // 512
#define SWARP 8                   // warps per stats block
#define SCH   16                  // channels per stats warp

#define ABAND 4                   // apply: rows per band
#define ABPX  (ABAND * W_)        // 512
#define ACH   8                   // channels per apply block (1 per warp)

typedef unsigned long long u64;

// ---------------- device scratch ----------------------------------------------
__device__ float g_y[B_ * C_];
__device__ float g_gate[B_ * C_];
__device__ float g_aggw[B_ * C_ * 9];
__device__ float g_ps[2][B_ * HW_];   // partial sum   (per channel-half)
__device__ float g_pq[2][B_ * HW_];   // partial sumsq

__device__ __forceinline__ float sigmoidf_(float v) {
    return 1.0f / (1.0f + __expf(-v));
}

// tanh-form GELU using MUFU.TANH: ~6 instructions, no divergence.
// |err| <= ~1e-3 abs worst case (formula 3e-4 + tanh.approx 6e-4), ~1e-4 norm.
__device__ __forceinline__ float gelu_f(float v) {
    const float v2 = v * v;
    const float t1 = fmaf(0.0356774081f, v2, 0.7978845608f);  // sqrt(2/pi)*(1+0.044715 v^2)
    const float inner = v * t1;
    float th;
    asm("tanh.approx.f32 %0, %1;" : "=f"(th) : "f"(inner));
    const float hv = 0.5f * v;
    return fmaf(hv, th, hv);
}

// ---------------- packed f32x2 helpers ------------------------------------------
__device__ __forceinline__ u64 pk2(float lo, float hi) {
    u64 r;
    asm("mov.b64 %0, {%1, %2};" : "=l"(r)
        : "r"(__float_as_uint(lo)), "r"(__float_as_uint(hi)));
    return r;
}
__device__ __forceinline__ float2 up2(u64 v) {
    unsigned int lo, hi;
    asm("mov.b64 {%0, %1}, %2;" : "=r"(lo), "=r"(hi) : "l"(v));
    return make_float2(__uint_as_float(lo), __uint_as_float(hi));
}
__device__ __forceinline__ u64 f2fma(u64 a, u64 b, u64 c) {
    u64 d;
    asm("fma.rn.f32x2 %0, %1, %2, %3;" : "=l"(d) : "l"(a), "l"(b), "l"(c));
    return d;
}
__device__ __forceinline__ u64 f2mul(u64 a, u64 b) {
    u64 d;
    asm("mul.rn.f32x2 %0, %1, %2;" : "=l"(d) : "l"(a), "l"(b));
    return d;
}
__device__ __forceinline__ u64 f2add(u64 a, u64 b) {
    u64 d;
    asm("add.rn.f32x2 %0, %1, %2;" : "=l"(d) : "l"(a), "l"(b));
    return d;
}

// ---------------- K1: global average pool per (b,c) ---------------------------
__global__ void gap_kernel(const float* __restrict__ x) {
    __shared__ float red[8];
    const int bc = blockIdx.x;
    const float4* xp = reinterpret_cast<const float4*>(x + (size_t)bc * HW_);
    float s = 0.f;
#pragma unroll
    for (int i = 0; i < 16; i++) {
        float4 v = xp[threadIdx.x + 256 * i];
        s += (v.x + v.y) + (v.z + v.w);
    }
#pragma unroll
    for (int o = 16; o; o >>= 1) s += __shfl_xor_sync(0xffffffffu, s, o);
    if ((threadIdx.x & 31) == 0) red[threadIdx.x >> 5] = s;
    __syncthreads();
    if (threadIdx.x < 8) {
        s = red[threadIdx.x];
#pragma unroll
        for (int o = 4; o; o >>= 1) s += __shfl_xor_sync(0x000000ffu, s, o);
        if (threadIdx.x == 0) g_y[bc] = s * (1.0f / (float)HW_);
    }
}

// ---------------- K2: ECA gate + MLP + softmax + kernel aggregation -----------
__global__ void attn_kernel(const float* __restrict__ w1, const float* __restrict__ b1,
                            const float* __restrict__ w2, const float* __restrict__ b2,
                            const float* __restrict__ kw, const float* __restrict__ eca) {
    const int b = blockIdx.x;
    const int t = threadIdx.x;
    __shared__ float ysm[C_ + 2];
    __shared__ float psm[C_];
    __shared__ float hsm[C_];
    __shared__ float lsm[K_];
    __shared__ float alph[K_];

    ysm[t + 1] = g_y[b * C_ + t];
    if (t == 0) { ysm[0] = 0.f; ysm[C_ + 1] = 0.f; }
    __syncthreads();

    const float e0 = eca[0], e1 = eca[1], e2 = eca[2];
    float gate = sigmoidf_(e0 * ysm[t] + e1 * ysm[t + 1] + e2 * ysm[t + 2]);
    g_gate[b * C_ + t] = gate;
    psm[t] = gate * ysm[t + 1];
    __syncthreads();

    float acc = b1[t];
    for (int c = 0; c < C_; c++) acc += psm[c] * w1[c * C_ + t];
    hsm[t] = 0.5f * acc * (1.0f + erff(acc * 0.70710678118654752f));  // exact here
    __syncthreads();

    if (t < K_) {
        float l = b2[t];
        for (int c = 0; c < C_; c++) l += hsm[c] * w2[c * K_ + t];
        lsm[t] = l;
    }
    __syncthreads();

    if (t == 0) {
        float m = lsm[0];
#pragma unroll
        for (int k = 1; k < K_; k++) m = fmaxf(m, lsm[k]);
        float s = 0.f;
#pragma unroll
        for (int k = 0; k < K_; k++) { float e = __expf(lsm[k] - m); alph[k] = e; s += e; }
        float inv = 1.0f / s;
#pragma unroll
        for (int k = 0; k < K_; k++) alph[k] *= inv;
    }
    __syncthreads();

    for (int idx = t; idx < C_ * 9; idx += 256) {
        float v = 0.f;
#pragma unroll
        for (int k = 0; k < K_; k++) v += alph[k] * kw[k * (C_ * 9) + idx];
        g_aggw[b * (C_ * 9) + idx] = v;
    }
}

// ---------------- scalar sliding-window helpers (apply kernel) -----------------
template <int NR> struct WinT { float4 r[NR]; };

template <int NR>
__device__ __forceinline__ void load_winN(const float4* __restrict__ xc4,
                                          int h0, int lane, WinT<NR>& w) {
#pragma unroll
    for (int r = 0; r < NR; r++) {
        const int gh = h0 - 1 + r;
        if (gh >= 0 && gh < H_) w.r[r] = xc4[gh * (W_ / 4) + lane];
        else                    w.r[r] = make_float4(0.f, 0.f, 0.f, 0.f);
    }
}

template <int NR>
__device__ __forceinline__ void shiftsN(const WinT<NR>& win, float* L, float* Rv, int lane) {
#pragma unroll
    for (int r = 0; r < NR; r++) {
        float l  = __shfl_up_sync(0xffffffffu, win.r[r].w, 1);
        float rr = __shfl_down_sync(0xffffffffu, win.r[r].x, 1);
        L[r]  = (lane == 0)  ? 0.f : l;
        Rv[r] = (lane == 31) ? 0.f : rr;
    }
}

template <int NR>
__device__ __forceinline__ float4 conv_rowN(const WinT<NR>& win, const float* L,
                                            const float* Rv, const float* w, int j) {
    float4 a;
    const float4 v0 = win.r[j], v1 = win.r[j + 1], v2 = win.r[j + 2];
    a.x  = w[0]*L[j]   + w[1]*v0.x + w[2]*v0.y;
    a.y  = w[0]*v0.x   + w[1]*v0.y + w[2]*v0.z;
    a.z  = w[0]*v0.y   + w[1]*v0.z + w[2]*v0.w;
    a.w  = w[0]*v0.z   + w[1]*v0.w + w[2]*Rv[j];
    a.x += w[3]*L[j+1] + w[4]*v1.x + w[5]*v1.y;
    a.y += w[3]*v1.x   + w[4]*v1.y + w[5]*v1.z;
    a.z += w[3]*v1.y   + w[4]*v1.z + w[5]*v1.w;
    a.w += w[3]*v1.z   + w[4]*v1.w + w[5]*Rv[j+1];
    a.x += w[6]*L[j+2] + w[7]*v2.x + w[8]*v2.y;
    a.y += w[6]*v2.x   + w[7]*v2.y + w[8]*v2.z;
    a.z += w[6]*v2.y   + w[7]*v2.z + w[8]*v2.w;
    a.w += w[6]*v2.z   + w[7]*v2.w + w[8]*Rv[j+2];
    return a;
}

// ---------------- packed row representation (stats kernel) ---------------------
struct PRow { u64 n0, n1, s0, s1, s2; };

__device__ __forceinline__ PRow make_prow(float4 v, int lane) {
    float l  = __shfl_up_sync(0xffffffffu, v.w, 1);
    float r  = __shfl_down_sync(0xffffffffu, v.x, 1);
    if (lane == 0)  l = 0.f;
    if (lane == 31) r = 0.f;
    PRow p;
    p.n0 = pk2(v.x, v.y);
    p.n1 = pk2(v.z, v.w);
    p.s0 = pk2(l,   v.x);
    p.s1 = pk2(v.y, v.z);
    p.s2 = pk2(v.w, r);
    return p;
}

__device__ __forceinline__ void conv_pairP(const PRow& p0, const PRow& p1, const PRow& p2,
                                           const u64* wp, u64& A, u64& B) {
    u64 a = f2mul(wp[0], p0.s0);
    a = f2fma(wp[1], p0.n0, a);
    a = f2fma(wp[2], p0.s1, a);
    a = f2fma(wp[3], p1.s0, a);
    a = f2fma(wp[4], p1.n0, a);
    a = f2fma(wp[5], p1.s1, a);
    a = f2fma(wp[6], p2.s0, a);
    a = f2fma(wp[7], p2.n0, a);
    a = f2fma(wp[8], p2.s1, a);
    u64 b = f2mul(wp[0], p0.s1);
    b = f2fma(wp[1], p0.n1, b);
    b = f2fma(wp[2], p0.s2, b);
    b = f2fma(wp[3], p1.s1, b);
    b = f2fma(wp[4], p1.n1, b);
    b = f2fma(wp[5], p1.s2, b);
    b = f2fma(wp[6], p2.s1, b);
    b = f2fma(wp[7], p2.n1, b);
    b = f2fma(wp[8], p2.s2, b);
    A = a; B = b;
}

// ---------------- K3a: partial LN stats over half the channels -----------------
// (R9 config, unchanged)
__global__ void __launch_bounds__(256, 2)
stats_kernel(const float* __restrict__ x) {
    __shared__ float s_w[128 * 9];
    __shared__ float s_sum[SWARP * SBPX];
    __shared__ float s_sq[SWARP * SBPX];

    const int tid  = threadIdx.x;
    const int warp = tid >> 5;
    const int lane = tid & 31;
    const int cg   = blockIdx.x;           // 0 or 1: channel half
    const int b    = blockIdx.y;
    const int h0   = blockIdx.z * SBAND;

    for (int i = tid; i < 128 * 9; i += 256) {
        const int gi = cg * 128 * 9 + i;
        s_w[i] = g_aggw[b * (C_ * 9) + gi] * g_gate[b * C_ + cg * 128 + i / 9];
    }
    __syncthreads();

    const int c0 = cg * 128 + warp * SCH;
    const float4* xb = reinterpret_cast<const float4*>(x + ((size_t)b * C_ + c0) * HW_);

    u64 sA[SBAND], sB[SBAND], qA[SBAND], qB[SBAND];
#pragma unroll
    for (int j = 0; j < SBAND; j++) { sA[j] = 0ull; sB[j] = 0ull; qA[j] = 0ull; qB[j] = 0ull; }

    for (int ci = 0; ci < SCH; ci++) {
        const float4* xc = xb + (size_t)ci * (HW_ / 4);
        float4 v[6];
#pragma unroll
        for (int r = 0; r < 6; r++) {
            const int gh = h0 - 1 + r;
            if (gh >= 0 && gh < H_) v[r] = xc[gh * (W_ / 4) + lane];
            else                    v[r] = make_float4(0.f, 0.f, 0.f, 0.f);
        }
        const float* wc = s_w + (warp * SCH + ci) * 9;
        u64 wp[9];
#pragma unroll
        for (int i = 0; i < 9; i++) { const float w = wc[i]; wp[i] = pk2(w, w); }

        u64 A, Bv;
        PRow p0 = make_prow(v[0], lane);
        PRow p1 = make_prow(v[1], lane);
        PRow p2 = make_prow(v[2], lane);
        conv_pairP(p0, p1, p2, wp, A, Bv);
        sA[0] = f2add(sA[0], A);  qA[0] = f2fma(A, A, qA[0]);
        sB[0] = f2add(sB[0], Bv); qB[0] = f2fma(Bv, Bv, qB[0]);

        p0 = make_prow(v[3], lane);
        conv_pairP(p1, p2, p0, wp, A, Bv);
        sA[1] = f2add(sA[1], A);  qA[1] = f2fma(A, A, qA[1]);
        sB[1] = f2add(sB[1], Bv); qB[1] = f2fma(Bv, Bv, qB[1]);

        p1 = make_prow(v[4], lane);
        conv_pairP(p2, p0, p1, wp, A, Bv);
        sA[2] = f2add(sA[2], A);  qA[2] = f2fma(A, A, qA[2]);
        sB[2] = f2add(sB[2], Bv); qB[2] = f2fma(Bv, Bv, qB[2]);

        p2 = make_prow(v[5], lane);
        conv_pairP(p0, p1, p2, wp, A, Bv);
        sA[3] = f2add(sA[3], A);  qA[3] = f2fma(A, A, qA[3]);
        sB[3] = f2add(sB[3], Bv); qB[3] = f2fma(Bv, Bv, qB[3]);
    }

#pragma unroll
    for (int j = 0; j < SBAND; j++) {
        const int px = j * W_ + lane * 4;
        const float2 a0 = up2(sA[j]), b0 = up2(sB[j]);
        const float2 a1 = up2(qA[j]), b1 = up2(qB[j]);
        *reinterpret_cast<float4*>(&s_sum[warp * SBPX + px]) = make_float4(a0.x, a0.y, b0.x, b0.y);
        *reinterpret_cast<float4*>(&s_sq[warp * SBPX + px])  = make_float4(a1.x, a1.y, b1.x, b1.y);
    }
    __syncthreads();

    for (int px = tid; px < SBPX; px += 256) {
        float s = 0.f, q = 0.f;
#pragma unroll
        for (int w = 0; w < SWARP; w++) {
            s += s_sum[w * SBPX + px];
            q += s_sq[w * SBPX + px];
        }
        const size_t o = (size_t)b * HW_ + h0 * W_ + px;
        g_ps[cg][o] = s;
        g_pq[cg][o] = q;
    }
}

// ---------------- K3b: conv recompute + LN + GELU + residual -------------------
// block = (band, b, channel-group). R8 grid order. tanh-MUFU gelu.
__global__ void __launch_bounds__(256, 4)
apply_kernel(const float* __restrict__ x, const float* __restrict__ gamma,
             const float* __restrict__ beta, float* __restrict__ out) {
    __shared__ float s_w[ACH * 9];
    __shared__ float s_g[ACH];
    __shared__ float s_b[ACH];
    __shared__ float s_mu[ABPX];
    __shared__ float s_rs[ABPX];

    const int tid  = threadIdx.x;
    const int warp = tid >> 5;
    const int lane = tid & 31;
    const int h0   = blockIdx.x * ABAND;
    const int b    = blockIdx.y;
    const int cz   = blockIdx.z * ACH;      // first channel of this block

    if (tid < ACH * 9)
        s_w[tid] = g_aggw[b * (C_ * 9) + cz * 9 + tid] * g_gate[b * C_ + cz + tid / 9];
    if (tid >= 96 && tid < 96 + ACH)   s_g[tid - 96]  = gamma[cz + tid - 96];
    if (tid >= 128 && tid < 128 + ACH) s_b[tid - 128] = beta[cz + tid - 128];
    // combine partial stats -> mu / rstd for this band (512 px)
    for (int px = tid; px < ABPX; px += 256) {
        const size_t o = (size_t)b * HW_ + h0 * W_ + px;
        const float s = g_ps[0][o] + g_ps[1][o];
        const float q = g_pq[0][o] + g_pq[1][o];
        const float mu  = s * (1.0f / (float)C_);
        const float var = q * (1.0f / (float)C_) - mu * mu;
        s_mu[px] = mu;
        s_rs[px] = rsqrtf(var + 1e-6f);
    }
    __syncthreads();

    const int c = cz + warp;
    const float4* xb = reinterpret_cast<const float4*>(x + ((size_t)b * C_ + c) * HW_);
    float4* ob = reinterpret_cast<float4*>(out + ((size_t)b * C_ + c) * HW_);

    WinT<6> win;
    load_winN<6>(xb, h0, lane, win);
    float L[6], Rv[6];
    shiftsN<6>(win, L, Rv, lane);
    float w[9];
#pragma unroll
    for (int i = 0; i < 9; i++) w[i] = s_w[warp * 9 + i];
    const float gm = s_g[warp];
    const float bt = s_b[warp];

#pragma unroll
    for (int j = 0; j < ABAND; j++) {
        float4 a = conv_rowN<6>(win, L, Rv, w, j);
        const float4 mu4 = *reinterpret_cast<const float4*>(&s_mu[j * W_ + lane * 4]);
        const float4 rs4 = *reinterpret_cast<const float4*>(&s_rs[j * W_ + lane * 4]);
        const float4 res = win.r[j + 1];            // center row == residual x
        float4 o;
        o.x = gelu_f((a.x - mu4.x) * rs4.x * gm + bt) + res.x;
        o.y = gelu_f((a.y - mu4.y) * rs4.y * gm + bt) + res.y;
        o.z = gelu_f((a.z - mu4.z) * rs4.z * gm + bt) + res.z;
        o.w = gelu_f((a.w - mu4.w) * rs4.w * gm + bt) + res.w;
        ob[(size_t)(h0 + j) * (W_ / 4) + lane] = o;
    }
}

// ---------------- launcher -----------------------------------------------------
extern "C" void kernel_launch(void* const* d_in, const int* in_sizes, int n_in,
                              void* d_out, int out_size) {
    const float* x     = (const float*)d_in[0];
    const float* w1    = (const float*)d_in[1];
    const float* b1    = (const float*)d_in[2];
    const float* w2    = (const float*)d_in[3];
    const float* b2    = (const float*)d_in[4];
    const float* kw    = (const float*)d_in[5];
    const float* eca   = (const float*)d_in[6];
    const float* gamma = (const float*)d_in[7];
    const float* beta  = (const float*)d_in[8];
    float* out = (float*)d_out;

    gap_kernel<<<B_ * C_, 256>>>(x);
    attn_kernel<<<B_, 256>>>(w1, b1, w2, b2, kw, eca);
    dim3 sgrid(2, B_, H_ / SBAND);
    stats_kernel<<<sgrid, 256>>>(x);
    dim3 agrid(H_ / ABAND, B_, C_ / ACH);
    apply_kernel<<<agrid, 256>>>(x, gamma, beta, out);
}